// round 4
// baseline (speedup 1.0000x reference)
#include <cuda_runtime.h>
#include <cuda_bf16.h>

#define NN   256
#define BB   8
#define SS   14
#define BS   (BB*SS)
#define NDAT 12   // S - len(PILOTS)

// Scratch: h_freq = FFT(x) * conj(zc), complex interleaved
__device__ float2 g_h[BS * NN];

// ---------------------------------------------------------------------------
// Kernel 1: 256-point DFT per (b,s) + multiply by conj(zc).
// ---------------------------------------------------------------------------
__global__ void __launch_bounds__(NN) dft_kernel(const float* __restrict__ xr,
                                                 const float* __restrict__ xi,
                                                 const float* __restrict__ zr,
                                                 const float* __restrict__ zi)
{
    __shared__ float2 xs[NN];
    __shared__ float2 tw[NN];
    const int bs = blockIdx.x;
    const int k  = threadIdx.x;

    xs[k] = make_float2(xr[bs * NN + k], xi[bs * NN + k]);
    // tw[t] = exp(-2*pi*i * t / 256)
    float s, c;
    sincospif(-(float)k * (1.0f / 128.0f), &s, &c);
    tw[k] = make_float2(c, s);
    __syncthreads();

    float re = 0.0f, im = 0.0f;
#pragma unroll 8
    for (int n = 0; n < NN; n++) {
        const int t = (k * n) & (NN - 1);
        const float2 w = tw[t];
        const float2 v = xs[n];
        re = fmaf(v.x, w.x, fmaf(-v.y, w.y, re));
        im = fmaf(v.x, w.y, fmaf( v.y, w.x, im));
    }

    // multiply by conj(zc[k]) = (zr, -zi)
    const float a = zr[k];
    const float b = -zi[k];
    g_h[bs * NN + k] = make_float2(re * a - im * b, re * b + im * a);
}

// ---------------------------------------------------------------------------
// Kernel 2: out[b,s,n] = Re( sum_m cov[idx][n][m] * h[b,s,m] )
//   Re = sum_m ( cr*h.re - ci*h.im )
// Grid: BS*8 blocks; each block = one (b,s) + 32 rows. 256 threads = 8 warps,
// each warp does 4 rows. Warp streams 1KB cr-row + 1KB ci-row coalesced.
// ---------------------------------------------------------------------------
__global__ void __launch_bounds__(256) matvec_kernel(const float* __restrict__ cr,
                                                     const float* __restrict__ ci,
                                                     const int*   __restrict__ shift,
                                                     const int*   __restrict__ gidx,
                                                     float*       __restrict__ out)
{
    __shared__ float2 hs[NN];
    const int blk     = blockIdx.x;
    const int bs      = blk >> 3;
    const int rowBase = (blk & 7) * 32;
    const int b       = bs / SS;
    const int s       = bs % SS;
    const int tid     = threadIdx.x;

    hs[tid] = g_h[bs * NN + tid];

    const int g   = gidx[s];
    const int idx = (g == 0) ? 0 : shift[b * NDAT + g - 1];
    __syncthreads();

    const int w    = tid >> 5;
    const int lane = tid & 31;

    // Each lane owns m = lane*8 .. lane*8+7; hoist h into registers
    float2 h[8];
#pragma unroll
    for (int j = 0; j < 8; j++) h[j] = hs[lane * 8 + j];

    const size_t base = (size_t)idx * NN * NN;
    const float* crb = cr + base;
    const float* cib = ci + base;

#pragma unroll
    for (int r = 0; r < 4; r++) {
        const int row = rowBase + w * 4 + r;
        const float4* crp = (const float4*)(crb + (size_t)row * NN) + lane * 2;
        const float4* cip = (const float4*)(cib + (size_t)row * NN) + lane * 2;

        float re = 0.0f;
#pragma unroll
        for (int j = 0; j < 2; j++) {
            const float4 a = crp[j];
            const float4 c = cip[j];
            const float2 h0 = h[j * 4 + 0];
            const float2 h1 = h[j * 4 + 1];
            const float2 h2 = h[j * 4 + 2];
            const float2 h3 = h[j * 4 + 3];
            re = fmaf(a.x, h0.x, fmaf(-c.x, h0.y, re));
            re = fmaf(a.y, h1.x, fmaf(-c.y, h1.y, re));
            re = fmaf(a.z, h2.x, fmaf(-c.z, h2.y, re));
            re = fmaf(a.w, h3.x, fmaf(-c.w, h3.y, re));
        }

        // warp reduction
#pragma unroll
        for (int o = 16; o > 0; o >>= 1)
            re += __shfl_xor_sync(0xffffffffu, re, o);

        if (lane == 0) out[bs * NN + row] = re;
    }
}

extern "C" void kernel_launch(void* const* d_in, const int* in_sizes, int n_in,
                              void* d_out, int out_size)
{
    // Binding confirmed by R2 fingerprint: dict/parameter order.
    const float* xr    = (const float*)d_in[0];
    const float* xi    = (const float*)d_in[1];
    const float* cr    = (const float*)d_in[2];
    const float* ci    = (const float*)d_in[3];
    const float* zr    = (const float*)d_in[4];
    const float* zi    = (const float*)d_in[5];
    const int*   shift = (const int*)d_in[6];
    const int*   gidx  = (const int*)d_in[7];

    dft_kernel<<<BS, NN>>>(xr, xi, zr, zi);
    matvec_kernel<<<BS * 8, 256>>>(cr, ci, shift, gidx, (float*)d_out);
}

// round 5
// speedup vs baseline: 1.4289x; 1.4289x over previous
#include <cuda_runtime.h>
#include <cuda_bf16.h>

#define NN   256
#define BB   8
#define SS   14
#define BS   (BB*SS)
#define NDAT 12   // S - len(PILOTS)

// ---------------------------------------------------------------------------
// Fused kernel: per block = one (b,s) x 32 rows of the matvec.
// Phase 1: 256-pt DFT of x[b,s] via two-stage radix-16 (+ conj(zc)) -> smem h.
//          (redundant across the 8 blocks of a bs; trivially cheap)
// Phase 2: out[b,s,row] = Re( sum_m cov[idx][row][m] * h[m] )
//          full 16-float4 prefetch per warp-tile for max MLP.
// ---------------------------------------------------------------------------
__global__ void __launch_bounds__(256) fused_kernel(const float* __restrict__ xr,
                                                    const float* __restrict__ xi,
                                                    const float* __restrict__ cr,
                                                    const float* __restrict__ ci,
                                                    const float* __restrict__ zr,
                                                    const float* __restrict__ zi,
                                                    const int*   __restrict__ shift,
                                                    const int*   __restrict__ gidx,
                                                    float*       __restrict__ out)
{
    __shared__ float2 xs[16 * 17];   // x transposed [n0][n1], padded
    __shared__ float2 aa[17 * 16];   // stage-A output [n0][k0], padded
    __shared__ float2 hs[NN];
    __shared__ float2 w16[16];

    const int blk     = blockIdx.x;
    const int bs      = blk >> 3;
    const int rowBase = (blk & 7) * 32;
    const int b       = bs / SS;
    const int s       = bs % SS;
    const int tid     = threadIdx.x;

    // ---- load x (transposed for conflict-light stage A) + W16 table ----
    {
        float2 xv = make_float2(xr[bs * NN + tid], xi[bs * NN + tid]);
        xs[(tid & 15) * 17 + (tid >> 4)] = xv;   // xs[n0][n1], n = 16*n1 + n0
        if (tid < 16) {
            float sn, cs;
            sincospif(-(float)tid * 0.125f, &sn, &cs);   // e^{-2pi i t/16}
            w16[tid] = make_float2(cs, sn);
        }
    }
    __syncthreads();

    // ---- stage A: A'[k0][n0] = (sum_n1 x[16n1+n0] W16^{k0 n1}) * W256^{k0 n0}
    {
        const int k0 = tid >> 4, n0 = tid & 15;
        float ar = 0.0f, ai = 0.0f;
#pragma unroll
        for (int n1 = 0; n1 < 16; n1++) {
            const float2 v = xs[n0 * 17 + n1];
            const float2 w = w16[(k0 * n1) & 15];
            ar = fmaf(v.x, w.x, fmaf(-v.y, w.y, ar));
            ai = fmaf(v.x, w.y, fmaf( v.y, w.x, ai));
        }
        float sn, cs;
        sincospif(-(float)(k0 * n0) * (1.0f / 128.0f), &sn, &cs);  // W256^{k0 n0}
        aa[n0 * 17 + k0] = make_float2(ar * cs - ai * sn, ar * sn + ai * cs);
    }
    __syncthreads();

    // ---- stage B: X[16k1+k0] = sum_n0 A'[k0][n0] W16^{k1 n0}; * conj(zc) ----
    {
        const int k0 = tid & 15, k1 = tid >> 4;
        float Xr = 0.0f, Xi = 0.0f;
#pragma unroll
        for (int n0 = 0; n0 < 16; n0++) {
            const float2 v = aa[n0 * 17 + k0];
            const float2 w = w16[(k1 * n0) & 15];
            Xr = fmaf(v.x, w.x, fmaf(-v.y, w.y, Xr));
            Xi = fmaf(v.x, w.y, fmaf( v.y, w.x, Xi));
        }
        const float a  = zr[tid];
        const float bq = -zi[tid];
        hs[tid] = make_float2(Xr * a - Xi * bq, Xr * bq + Xi * a);
    }

    const int g   = gidx[s];
    const int idx = (g == 0) ? 0 : shift[b * NDAT + g - 1];
    __syncthreads();

    // ---- phase 2: matvec, 8 warps x 4 rows, full prefetch ----
    const int w    = tid >> 5;
    const int lane = tid & 31;

    float2 h[8];
#pragma unroll
    for (int j = 0; j < 8; j++) h[j] = hs[lane * 8 + j];

    const size_t base = (size_t)idx * NN * NN;
    const float4* cr4 = (const float4*)(cr + base);
    const float4* ci4 = (const float4*)(ci + base);
    const int row0 = rowBase + w * 4;

    // Prefetch all 16 float4 (4 rows x (2 cr + 2 ci)) for deep MLP
    float4 A[4][2], C[4][2];
#pragma unroll
    for (int r = 0; r < 4; r++) {
#pragma unroll
        for (int j = 0; j < 2; j++) {
            A[r][j] = cr4[(size_t)(row0 + r) * 64 + lane * 2 + j];
            C[r][j] = ci4[(size_t)(row0 + r) * 64 + lane * 2 + j];
        }
    }

#pragma unroll
    for (int r = 0; r < 4; r++) {
        float re = 0.0f;
#pragma unroll
        for (int j = 0; j < 2; j++) {
            const float4 a = A[r][j];
            const float4 c = C[r][j];
            re = fmaf(a.x, h[j*4+0].x, fmaf(-c.x, h[j*4+0].y, re));
            re = fmaf(a.y, h[j*4+1].x, fmaf(-c.y, h[j*4+1].y, re));
            re = fmaf(a.z, h[j*4+2].x, fmaf(-c.z, h[j*4+2].y, re));
            re = fmaf(a.w, h[j*4+3].x, fmaf(-c.w, h[j*4+3].y, re));
        }
#pragma unroll
        for (int o = 16; o > 0; o >>= 1)
            re += __shfl_xor_sync(0xffffffffu, re, o);
        if (lane == 0) out[bs * NN + row0 + r] = re;
    }
}

extern "C" void kernel_launch(void* const* d_in, const int* in_sizes, int n_in,
                              void* d_out, int out_size)
{
    const float* xr    = (const float*)d_in[0];
    const float* xi    = (const float*)d_in[1];
    const float* cr    = (const float*)d_in[2];
    const float* ci    = (const float*)d_in[3];
    const float* zr    = (const float*)d_in[4];
    const float* zi    = (const float*)d_in[5];
    const int*   shift = (const int*)d_in[6];
    const int*   gidx  = (const int*)d_in[7];

    fused_kernel<<<BS * 8, 256>>>(xr, xi, cr, ci, zr, zi, shift, gidx,
                                  (float*)d_out);
}

// round 6
// speedup vs baseline: 1.6250x; 1.1373x over previous
#include <cuda_runtime.h>
#include <cuda_bf16.h>

#define NN   256
#define BB   8
#define SS   14
#define BS   (BB*SS)
#define NDAT 12   // S - len(PILOTS)

// ---------------------------------------------------------------------------
// Fused streaming kernel.
// Grid = BS*4 blocks; block = one (b,s) x 64 rows = 8 tiles of 8 rows
// (one row per warp per tile), double-buffered prefetch so each block keeps
// loads in flight for its entire 128 KB cov stream.
// Phase 1 (256-pt DFT via radix-16 x radix-16 + conj(zc)) overlaps with the
// tile-0 load latency.
// ---------------------------------------------------------------------------
__global__ void __launch_bounds__(256, 3)
fused_kernel(const float* __restrict__ xr,
             const float* __restrict__ xi,
             const float* __restrict__ cr,
             const float* __restrict__ ci,
             const float* __restrict__ zr,
             const float* __restrict__ zi,
             const int*   __restrict__ shift,
             const int*   __restrict__ gidx,
             float*       __restrict__ out)
{
    __shared__ float2 xs[16 * 17];   // x transposed [n0][n1], padded
    __shared__ float2 aa[17 * 16];   // stage-A output [n0][k0], padded
    __shared__ float2 hs[NN];
    __shared__ float2 w16[16];

    const int blk     = blockIdx.x;
    const int bs      = blk >> 2;
    const int rowBase = (blk & 3) * 64;
    const int b       = bs / SS;
    const int s       = bs % SS;
    const int tid     = threadIdx.x;
    const int w       = tid >> 5;
    const int lane    = tid & 31;

    // ---- resolve cov index early so tile-0 loads can issue before the DFT ----
    const int g   = __ldg(&gidx[s]);
    const int idx = (g == 0) ? 0 : __ldg(&shift[b * NDAT + g - 1]);
    const size_t  base = (size_t)idx * NN * NN;
    const float4* cr4  = (const float4*)(cr + base);
    const float4* ci4  = (const float4*)(ci + base);

    // Double-buffered tile registers: [buf][half]
    float4 A[2][2], C[2][2];

    // ---- issue tile 0 (row = rowBase + w) ----
    {
        const size_t ro = (size_t)(rowBase + w) * 64 + lane * 2;
        A[0][0] = cr4[ro];  A[0][1] = cr4[ro + 1];
        C[0][0] = ci4[ro];  C[0][1] = ci4[ro + 1];
    }

    // ---- phase 1: DFT (overlaps with tile-0 memory latency) ----
    {
        float2 xv = make_float2(xr[bs * NN + tid], xi[bs * NN + tid]);
        xs[(tid & 15) * 17 + (tid >> 4)] = xv;   // xs[n0][n1], n = 16*n1 + n0
        if (tid < 16) {
            float sn, cs;
            sincospif(-(float)tid * 0.125f, &sn, &cs);   // e^{-2pi i t/16}
            w16[tid] = make_float2(cs, sn);
        }
    }
    __syncthreads();

    {   // stage A: A'[k0][n0] = (sum_n1 x[16n1+n0] W16^{k0 n1}) * W256^{k0 n0}
        const int k0 = tid >> 4, n0 = tid & 15;
        float ar = 0.0f, ai = 0.0f;
#pragma unroll
        for (int n1 = 0; n1 < 16; n1++) {
            const float2 v  = xs[n0 * 17 + n1];
            const float2 ww = w16[(k0 * n1) & 15];
            ar = fmaf(v.x, ww.x, fmaf(-v.y, ww.y, ar));
            ai = fmaf(v.x, ww.y, fmaf( v.y, ww.x, ai));
        }
        float sn, cs;
        sincospif(-(float)(k0 * n0) * (1.0f / 128.0f), &sn, &cs);
        aa[n0 * 17 + k0] = make_float2(ar * cs - ai * sn, ar * sn + ai * cs);
    }
    __syncthreads();

    {   // stage B: X[16k1+k0] = sum_n0 A'[k0][n0] W16^{k1 n0}; then * conj(zc)
        const int k0 = tid & 15, k1 = tid >> 4;
        float Xr = 0.0f, Xi = 0.0f;
#pragma unroll
        for (int n0 = 0; n0 < 16; n0++) {
            const float2 v  = aa[n0 * 17 + k0];
            const float2 ww = w16[(k1 * n0) & 15];
            Xr = fmaf(v.x, ww.x, fmaf(-v.y, ww.y, Xr));
            Xi = fmaf(v.x, ww.y, fmaf( v.y, ww.x, Xi));
        }
        const float a  = zr[tid];
        const float bq = -zi[tid];
        hs[tid] = make_float2(Xr * a - Xi * bq, Xr * bq + Xi * a);
    }
    __syncthreads();

    // h chunk for this lane (m = lane*8 .. lane*8+7)
    float2 h[8];
#pragma unroll
    for (int j = 0; j < 8; j++) h[j] = hs[lane * 8 + j];

    // ---- phase 2: 8-tile streaming loop, double buffered ----
#pragma unroll
    for (int t = 0; t < 8; t++) {
        const int cur = t & 1;
        if (t < 7) {   // issue next tile's loads into the other buffer
            const int nxt = cur ^ 1;
            const size_t ro = (size_t)(rowBase + (t + 1) * 8 + w) * 64 + lane * 2;
            A[nxt][0] = cr4[ro];  A[nxt][1] = cr4[ro + 1];
            C[nxt][0] = ci4[ro];  C[nxt][1] = ci4[ro + 1];
        }

        float re = 0.0f;
#pragma unroll
        for (int j = 0; j < 2; j++) {
            const float4 a = A[cur][j];
            const float4 c = C[cur][j];
            re = fmaf(a.x, h[j*4+0].x, fmaf(-c.x, h[j*4+0].y, re));
            re = fmaf(a.y, h[j*4+1].x, fmaf(-c.y, h[j*4+1].y, re));
            re = fmaf(a.z, h[j*4+2].x, fmaf(-c.z, h[j*4+2].y, re));
            re = fmaf(a.w, h[j*4+3].x, fmaf(-c.w, h[j*4+3].y, re));
        }

#pragma unroll
        for (int o = 16; o > 0; o >>= 1)
            re += __shfl_xor_sync(0xffffffffu, re, o);

        if (lane == 0) out[bs * NN + rowBase + t * 8 + w] = re;
    }
}

extern "C" void kernel_launch(void* const* d_in, const int* in_sizes, int n_in,
                              void* d_out, int out_size)
{
    const float* xr    = (const float*)d_in[0];
    const float* xi    = (const float*)d_in[1];
    const float* cr    = (const float*)d_in[2];
    const float* ci    = (const float*)d_in[3];
    const float* zr    = (const float*)d_in[4];
    const float* zi    = (const float*)d_in[5];
    const int*   shift = (const int*)d_in[6];
    const int*   gidx  = (const int*)d_in[7];

    fused_kernel<<<BS * 4, 256>>>(xr, xi, cr, ci, zr, zi, shift, gidx,
                                  (float*)d_out);
}

// round 7
// speedup vs baseline: 1.6575x; 1.0200x over previous
#include <cuda_runtime.h>
#include <cuda_bf16.h>

#define NN   256
#define BB   8
#define SS   14
#define BS   (BB*SS)
#define NDAT 12   // S - len(PILOTS)

// ---------------------------------------------------------------------------
// Fused streaming kernel, 3-stage ring prefetch.
// Grid = BS*4 blocks; block = one (b,s) x 64 rows = 8 tiles of 8 rows
// (one row per warp per tile). Ring keeps 2 tiles of loads in flight while
// computing, so DRAM latency is covered by MLP instead of stalling.
// Phase 1 (256-pt DFT via radix-16 x radix-16 + conj(zc)) overlaps the
// 3-tile pipeline fill.
// ---------------------------------------------------------------------------
__global__ void __launch_bounds__(256, 3)
fused_kernel(const float* __restrict__ xr,
             const float* __restrict__ xi,
             const float* __restrict__ cr,
             const float* __restrict__ ci,
             const float* __restrict__ zr,
             const float* __restrict__ zi,
             const int*   __restrict__ shift,
             const int*   __restrict__ gidx,
             float*       __restrict__ out)
{
    __shared__ float2 xs[16 * 17];   // x transposed [n0][n1], padded
    __shared__ float2 aa[17 * 16];   // stage-A output [n0][k0], padded
    __shared__ float2 hs[NN];
    __shared__ float2 w16[16];

    const int blk     = blockIdx.x;
    const int bs      = blk >> 2;
    const int rowBase = (blk & 3) * 64;
    const int b       = bs / SS;
    const int s       = bs % SS;
    const int tid     = threadIdx.x;
    const int w       = tid >> 5;
    const int lane    = tid & 31;

    // ---- resolve cov index early so prologue loads issue before the DFT ----
    const int g   = __ldg(&gidx[s]);
    const int idx = (g == 0) ? 0 : __ldg(&shift[b * NDAT + g - 1]);
    const size_t  base = (size_t)idx * NN * NN;
    const float4* cr4  = (const float4*)(cr + base);
    const float4* ci4  = (const float4*)(ci + base);

    // 3-stage ring buffers: stage p holds one row (4 float4) per lane
    float4 A[3][2], C[3][2];

    // ---- prologue: issue tiles 0..2 (rows rowBase + t*8 + w) ----
#pragma unroll
    for (int p = 0; p < 3; p++) {
        const size_t ro = (size_t)(rowBase + p * 8 + w) * 64 + lane * 2;
        A[p][0] = cr4[ro];  A[p][1] = cr4[ro + 1];
        C[p][0] = ci4[ro];  C[p][1] = ci4[ro + 1];
    }

    // ---- phase 1: DFT (overlaps the pipeline fill) ----
    {
        float2 xv = make_float2(xr[bs * NN + tid], xi[bs * NN + tid]);
        xs[(tid & 15) * 17 + (tid >> 4)] = xv;   // xs[n0][n1], n = 16*n1 + n0
        if (tid < 16) {
            float sn, cs;
            sincospif(-(float)tid * 0.125f, &sn, &cs);   // e^{-2pi i t/16}
            w16[tid] = make_float2(cs, sn);
        }
    }
    __syncthreads();

    {   // stage A: A'[k0][n0] = (sum_n1 x[16n1+n0] W16^{k0 n1}) * W256^{k0 n0}
        const int k0 = tid >> 4, n0 = tid & 15;
        float ar = 0.0f, ai = 0.0f;
#pragma unroll
        for (int n1 = 0; n1 < 16; n1++) {
            const float2 v  = xs[n0 * 17 + n1];
            const float2 ww = w16[(k0 * n1) & 15];
            ar = fmaf(v.x, ww.x, fmaf(-v.y, ww.y, ar));
            ai = fmaf(v.x, ww.y, fmaf( v.y, ww.x, ai));
        }
        float sn, cs;
        sincospif(-(float)(k0 * n0) * (1.0f / 128.0f), &sn, &cs);
        aa[n0 * 17 + k0] = make_float2(ar * cs - ai * sn, ar * sn + ai * cs);
    }
    __syncthreads();

    {   // stage B: X[16k1+k0] = sum_n0 A'[k0][n0] W16^{k1 n0}; then * conj(zc)
        const int k0 = tid & 15, k1 = tid >> 4;
        float Xr = 0.0f, Xi = 0.0f;
#pragma unroll
        for (int n0 = 0; n0 < 16; n0++) {
            const float2 v  = aa[n0 * 17 + k0];
            const float2 ww = w16[(k1 * n0) & 15];
            Xr = fmaf(v.x, ww.x, fmaf(-v.y, ww.y, Xr));
            Xi = fmaf(v.x, ww.y, fmaf( v.y, ww.x, Xi));
        }
        const float a  = zr[tid];
        const float bq = -zi[tid];
        hs[tid] = make_float2(Xr * a - Xi * bq, Xr * bq + Xi * a);
    }
    __syncthreads();

    // h chunk for this lane (m = lane*8 .. lane*8+7)
    float2 h[8];
#pragma unroll
    for (int j = 0; j < 8; j++) h[j] = hs[lane * 8 + j];

    // ---- phase 2: 8-tile streaming loop over the 3-stage ring ----
#pragma unroll
    for (int t = 0; t < 8; t++) {
        const int cur = t % 3;

        float re = 0.0f;
#pragma unroll
        for (int j = 0; j < 2; j++) {
            const float4 a = A[cur][j];
            const float4 c = C[cur][j];
            re = fmaf(a.x, h[j*4+0].x, fmaf(-c.x, h[j*4+0].y, re));
            re = fmaf(a.y, h[j*4+1].x, fmaf(-c.y, h[j*4+1].y, re));
            re = fmaf(a.z, h[j*4+2].x, fmaf(-c.z, h[j*4+2].y, re));
            re = fmaf(a.w, h[j*4+3].x, fmaf(-c.w, h[j*4+3].y, re));
        }

        // refill this stage with tile t+3 (keeps 2 tiles always in flight)
        if (t < 5) {
            const size_t ro = (size_t)(rowBase + (t + 3) * 8 + w) * 64 + lane * 2;
            A[cur][0] = cr4[ro];  A[cur][1] = cr4[ro + 1];
            C[cur][0] = ci4[ro];  C[cur][1] = ci4[ro + 1];
        }

#pragma unroll
        for (int o = 16; o > 0; o >>= 1)
            re += __shfl_xor_sync(0xffffffffu, re, o);

        if (lane == 0) out[bs * NN + rowBase + t * 8 + w] = re;
    }
}

extern "C" void kernel_launch(void* const* d_in, const int* in_sizes, int n_in,
                              void* d_out, int out_size)
{
    const float* xr    = (const float*)d_in[0];
    const float* xi    = (const float*)d_in[1];
    const float* cr    = (const float*)d_in[2];
    const float* ci    = (const float*)d_in[3];
    const float* zr    = (const float*)d_in[4];
    const float* zi    = (const float*)d_in[5];
    const int*   shift = (const int*)d_in[6];
    const int*   gidx  = (const int*)d_in[7];

    fused_kernel<<<BS * 4, 256>>>(xr, xi, cr, ci, zr, zi, shift, gidx,
                                  (float*)d_out);
}